// round 14
// baseline (speedup 1.0000x reference)
#include <cuda_runtime.h>

#define BATCH 4
#define CCH   32
#define HH    512
#define WW    960
#define HT    128
#define WT    240
#define HW    (HH*WW)      // 491520
#define HTWT  (HT*WT)      // 30720

#define WSEG   480                  // x-pixels per block (960 = 2 segments)
#define PADL   60                   // covers max disparity ~53
#define SWINP  576                  // padded window floats (mult of 4 & 32)
#define NF4    (SWINP/4)            // 144 float4 per channel row
#define CPASS  8                    // channels per pass
#define NPASS  (CCH/CPASS)          // 4
#define NTHR   512

__device__ __forceinline__ void cp_async16(void* smem_dst, const void* gsrc, unsigned src_sz)
{
    unsigned dst = (unsigned)__cvta_generic_to_shared(smem_dst);
    asm volatile("cp.async.cg.shared.global [%0], [%1], 16, %2;\n"
                 :: "r"(dst), "l"(gsrc), "r"(src_sz) : "memory");
}
__device__ __forceinline__ void cp_commit()  { asm volatile("cp.async.commit_group;\n" ::: "memory"); }
__device__ __forceinline__ void cp_wait_all(){ asm volatile("cp.async.wait_group 0;\n" ::: "memory"); }

__global__ __launch_bounds__(NTHR, 3)
void tile_warp_kernel(const float* __restrict__ tp,
                      const float* __restrict__ fl,
                      const float* __restrict__ fr,
                      float* __restrict__ out)
{
    __shared__ float s[2][CPASS * SWINP];   // 2 * 8 * 576 * 4 = 36864 B

    int t    = threadIdx.x;
    int warp = t >> 5;
    int lane = t & 31;
    int seg  = blockIdx.x & 1;
    int y    = (blockIdx.x >> 1) & (HH - 1);
    int b    = blockIdx.x >> 10;
    int xs   = seg * WSEG;
    int wbeg = xs - PADL;                    // multiple of 4 -> 16B aligned

    // ---- per-pixel setup (compute lanes only: t < 480) ----
    int x = xs + t;
    float w = 0.f, mm1 = 0.f, m0 = 0.f, mp1 = 0.f;
    int off = 1;
    if (t < WSEG) {
        int ht = y >> 2, wt = x >> 2;
        int i  = y & 3,  j  = x & 3;
        int tb = (b * 3 * HT + ht) * WT + wt;
        float d  = __ldg(tp + tb);
        float dx = __ldg(tp + tb + HTWT);
        float dy = __ldg(tp + tb + 2 * HTWT);

        float sx  = (float)x - d - ((float)j - 1.5f) * dx - ((float)i - 1.5f) * dy;
        float x0f = floorf(sx);
        w  = sx - x0f;
        int x0 = (int)x0f;

        mm1 = (sx >= -1.f && sx <= (float)(WW - 2)) ? 1.f : 0.f;
        m0  = (sx >=  0.f && sx <= (float)(WW - 1)) ? 1.f : 0.f;
        mp1 = (sx >=  1.f && sx <= (float)(WW))     ? 1.f : 0.f;

        off = min(max(x0 - wbeg, 1), SWINP - 3);   // smem-safe; masked if clamped
    }

    const float* frrow = fr + (size_t)b * CCH * HW + (size_t)y * WW;
    const float* flp   = fl + (size_t)b * CCH * HW + (size_t)y * WW + x;

    // staging role: warp w -> channel (w>>1), half-window (w&1)
    int sc    = warp >> 1;                 // 0..7
    int kbase = (warp & 1) * (NF4 / 2);    // 0 or 72
    const float* ssrc0 = frrow + (size_t)sc * HW + wbeg;

    auto stage = [&](int pp, int bb) {
        const float* src = ssrc0 + (size_t)pp * CPASS * HW;
        float* dst = &s[bb][sc * SWINP];
#pragma unroll
        for (int r = 0; r < 3; r++) {
            int k4 = kbase + lane + r * 32;
            if (k4 < kbase + NF4 / 2) {
                int gx = wbeg + 4 * k4;
                unsigned sz = (gx >= 0 && gx < WW) ? 16u : 0u;
                cp_async16(dst + 4 * k4, src + 4 * k4, sz);
            }
        }
        cp_commit();
    };

    float am1 = 0.f, a0 = 0.f, ap1 = 0.f;

    // ---- prologue: stage pass 0 + prefetch fea_l for pass 0 ----
    stage(0, 0);
    float a_cur[CPASS];
#pragma unroll
    for (int c = 0; c < CPASS; c++)
        a_cur[c] = (t < WSEG) ? __ldcs(flp + (size_t)c * HW) : 0.f;
    cp_wait_all();
    __syncthreads();

#pragma unroll
    for (int p = 0; p < NPASS; p++) {
        // issue staging for pass p+1 into the other buffer (async)
        if (p < NPASS - 1) stage(p + 1, (p + 1) & 1);

        // prefetch fea_l for pass p+1 (independent LDGs, a full pass to land)
        float a_nxt[CPASS];
#pragma unroll
        for (int c = 0; c < CPASS; c++) a_nxt[c] = 0.f;
        if (p < NPASS - 1 && t < WSEG) {
#pragma unroll
            for (int c = 0; c < CPASS; c++)
                a_nxt[c] = __ldcs(flp + (size_t)((p + 1) * CPASS + c) * HW);
        }

        // ---- compute pass p from buffer p&1 (smem + registers only) ----
        if (t < WSEG) {
            const float* buf = s[p & 1];
#pragma unroll
            for (int c = 0; c < CPASS; c++) {
                float a = a_cur[c];
                const float* q = buf + c * SWINP + off;
                float g0 = q[-1], g1 = q[0], g2 = q[1], g3 = q[2];
                am1 += fabsf(a - mm1 * (g2 + w * (g3 - g2)));   // dd=-1
                a0  += fabsf(a - m0  * (g1 + w * (g2 - g1)));   // dd= 0
                ap1 += fabsf(a - mp1 * (g0 + w * (g1 - g0)));   // dd=+1
            }
        }

#pragma unroll
        for (int c = 0; c < CPASS; c++) a_cur[c] = a_nxt[c];

        cp_wait_all();
        __syncthreads();
    }

    if (t < WSEG) {
        int ht = y >> 2, wt = x >> 2;
        int i  = y & 3,  j  = x & 3;
        int ob = (b * 48 * HT + ht) * WT + wt + (i * 4 + j) * HTWT;
        out[ob]             = am1;
        out[ob + 16 * HTWT] = a0;
        out[ob + 32 * HTWT] = ap1;
    }
}

extern "C" void kernel_launch(void* const* d_in, const int* in_sizes, int n_in,
                              void* d_out, int out_size)
{
    const float* tp = nullptr;
    const float* big[2] = {nullptr, nullptr};
    int nbig = 0;
    for (int k = 0; k < n_in; k++) {
        if (in_sizes[k] == BATCH * 3 * HTWT) {
            tp = (const float*)d_in[k];
        } else if (nbig < 2) {
            big[nbig++] = (const float*)d_in[k];
        }
    }
    const float* fl = big[0];
    const float* fr = big[1];
    float* out = (float*)d_out;

    int blocks = BATCH * HH * 2;   // 4096
    tile_warp_kernel<<<blocks, NTHR>>>(tp, fl, fr, out);
}

// round 15
// speedup vs baseline: 1.0006x; 1.0006x over previous
#include <cuda_runtime.h>

#define BATCH 4
#define CCH   32
#define HH    512
#define WW    960
#define HT    128
#define WT    240
#define HW    (HH*WW)      // 491520
#define HTWT  (HT*WT)      // 30720

#define WSEG   480                  // x-pixels per block (960 = 2 segments)
#define PADL   60                   // covers max disparity ~53
#define SWINP  576                  // padded window floats (mult of 4 & 32)
#define NF4    (SWINP/4)            // 144 float4 per channel row
#define CPASS  8                    // channels per pass
#define NPASS  (CCH/CPASS)          // 4
#define NTHR   512

__device__ __forceinline__ void cp_async16(void* smem_dst, const void* gsrc, unsigned src_sz)
{
    unsigned dst = (unsigned)__cvta_generic_to_shared(smem_dst);
    asm volatile("cp.async.cg.shared.global [%0], [%1], 16, %2;\n"
                 :: "r"(dst), "l"(gsrc), "r"(src_sz) : "memory");
}
__device__ __forceinline__ void cp_commit()  { asm volatile("cp.async.commit_group;\n" ::: "memory"); }
__device__ __forceinline__ void cp_wait_all(){ asm volatile("cp.async.wait_group 0;\n" ::: "memory"); }

__global__ __launch_bounds__(NTHR, 3)
void tile_warp_kernel(const float* __restrict__ tp,
                      const float* __restrict__ fl,
                      const float* __restrict__ fr,
                      float* __restrict__ out)
{
    __shared__ float s[2][CPASS * SWINP];   // 2 * 8 * 576 * 4 = 36864 B

    int t    = threadIdx.x;
    int warp = t >> 5;
    int lane = t & 31;
    int seg  = blockIdx.x & 1;
    int y    = (blockIdx.x >> 1) & (HH - 1);
    int b    = blockIdx.x >> 10;
    int xs   = seg * WSEG;
    int wbeg = xs - PADL;                    // multiple of 4 -> 16B aligned

    // ---- per-pixel setup (compute lanes only: t < 480) ----
    int x = xs + t;
    float w = 0.f, mm1 = 0.f, m0 = 0.f, mp1 = 0.f;
    int off = 1;
    if (t < WSEG) {
        int ht = y >> 2, wt = x >> 2;
        int i  = y & 3,  j  = x & 3;
        int tb = (b * 3 * HT + ht) * WT + wt;
        float d  = __ldg(tp + tb);
        float dx = __ldg(tp + tb + HTWT);
        float dy = __ldg(tp + tb + 2 * HTWT);

        float sx  = (float)x - d - ((float)j - 1.5f) * dx - ((float)i - 1.5f) * dy;
        float x0f = floorf(sx);
        w  = sx - x0f;
        int x0 = (int)x0f;

        mm1 = (sx >= -1.f && sx <= (float)(WW - 2)) ? 1.f : 0.f;
        m0  = (sx >=  0.f && sx <= (float)(WW - 1)) ? 1.f : 0.f;
        mp1 = (sx >=  1.f && sx <= (float)(WW))     ? 1.f : 0.f;

        off = min(max(x0 - wbeg, 1), SWINP - 3);   // smem-safe; masked if clamped
    }

    const float* frrow = fr + (size_t)b * CCH * HW + (size_t)y * WW;
    const float* flp   = fl + (size_t)b * CCH * HW + (size_t)y * WW + x;

    // staging role: warp w -> channel (w>>1), half-window (w&1)
    int sc    = warp >> 1;                 // 0..7
    int kbase = (warp & 1) * (NF4 / 2);    // 0 or 72
    const float* ssrc0 = frrow + (size_t)sc * HW + wbeg;

    auto stage = [&](int pp, int bb) {
        const float* src = ssrc0 + (size_t)pp * CPASS * HW;
        float* dst = &s[bb][sc * SWINP];
#pragma unroll
        for (int r = 0; r < 3; r++) {
            int k4 = kbase + lane + r * 32;
            if (k4 < kbase + NF4 / 2) {
                int gx = wbeg + 4 * k4;
                unsigned sz = (gx >= 0 && gx < WW) ? 16u : 0u;
                cp_async16(dst + 4 * k4, src + 4 * k4, sz);
            }
        }
        cp_commit();
    };

    float am1 = 0.f, a0 = 0.f, ap1 = 0.f;

    // ---- prologue: stage pass 0 + prefetch fea_l for pass 0 ----
    stage(0, 0);
    float a_cur[CPASS];
#pragma unroll
    for (int c = 0; c < CPASS; c++)
        a_cur[c] = (t < WSEG) ? __ldcs(flp + (size_t)c * HW) : 0.f;
    cp_wait_all();
    __syncthreads();

#pragma unroll
    for (int p = 0; p < NPASS; p++) {
        // issue staging for pass p+1 into the other buffer (async)
        if (p < NPASS - 1) stage(p + 1, (p + 1) & 1);

        // prefetch fea_l for pass p+1 (independent LDGs, a full pass to land)
        float a_nxt[CPASS];
#pragma unroll
        for (int c = 0; c < CPASS; c++) a_nxt[c] = 0.f;
        if (p < NPASS - 1 && t < WSEG) {
#pragma unroll
            for (int c = 0; c < CPASS; c++)
                a_nxt[c] = __ldcs(flp + (size_t)((p + 1) * CPASS + c) * HW);
        }

        // ---- compute pass p from buffer p&1 (smem + registers only) ----
        if (t < WSEG) {
            const float* buf = s[p & 1];
#pragma unroll
            for (int c = 0; c < CPASS; c++) {
                float a = a_cur[c];
                const float* q = buf + c * SWINP + off;
                float g0 = q[-1], g1 = q[0], g2 = q[1], g3 = q[2];
                am1 += fabsf(a - mm1 * (g2 + w * (g3 - g2)));   // dd=-1
                a0  += fabsf(a - m0  * (g1 + w * (g2 - g1)));   // dd= 0
                ap1 += fabsf(a - mp1 * (g0 + w * (g1 - g0)));   // dd=+1
            }
        }

#pragma unroll
        for (int c = 0; c < CPASS; c++) a_cur[c] = a_nxt[c];

        cp_wait_all();
        __syncthreads();
    }

    if (t < WSEG) {
        int ht = y >> 2, wt = x >> 2;
        int i  = y & 3,  j  = x & 3;
        int ob = (b * 48 * HT + ht) * WT + wt + (i * 4 + j) * HTWT;
        out[ob]             = am1;
        out[ob + 16 * HTWT] = a0;
        out[ob + 32 * HTWT] = ap1;
    }
}

extern "C" void kernel_launch(void* const* d_in, const int* in_sizes, int n_in,
                              void* d_out, int out_size)
{
    const float* tp = nullptr;
    const float* big[2] = {nullptr, nullptr};
    int nbig = 0;
    for (int k = 0; k < n_in; k++) {
        if (in_sizes[k] == BATCH * 3 * HTWT) {
            tp = (const float*)d_in[k];
        } else if (nbig < 2) {
            big[nbig++] = (const float*)d_in[k];
        }
    }
    const float* fl = big[0];
    const float* fr = big[1];
    float* out = (float*)d_out;

    int blocks = BATCH * HH * 2;   // 4096
    tile_warp_kernel<<<blocks, NTHR>>>(tp, fl, fr, out);
}

// round 16
// speedup vs baseline: 1.0010x; 1.0003x over previous
#include <cuda_runtime.h>

#define BATCH 4
#define CCH   32
#define HH    512
#define WW    960
#define HT    128
#define WT    240
#define HW    (HH*WW)      // 491520
#define HTWT  (HT*WT)      // 30720

#define WSEG   480                  // x-pixels per block (960 = 2 segments)
#define PADL   60                   // covers max disparity ~53
#define SWINP  576                  // padded window floats (mult of 4 & 32)
#define NF4    (SWINP/4)            // 144 float4 per channel row
#define CPASS  8                    // channels per pass
#define NPASS  (CCH/CPASS)          // 4
#define NTHR   512

__device__ __forceinline__ void cp_async16(void* smem_dst, const void* gsrc, unsigned src_sz)
{
    unsigned dst = (unsigned)__cvta_generic_to_shared(smem_dst);
    asm volatile("cp.async.cg.shared.global [%0], [%1], 16, %2;\n"
                 :: "r"(dst), "l"(gsrc), "r"(src_sz) : "memory");
}
__device__ __forceinline__ void cp_commit()  { asm volatile("cp.async.commit_group;\n" ::: "memory"); }
__device__ __forceinline__ void cp_wait_all(){ asm volatile("cp.async.wait_group 0;\n" ::: "memory"); }

__global__ __launch_bounds__(NTHR, 3)
void tile_warp_kernel(const float* __restrict__ tp,
                      const float* __restrict__ fl,
                      const float* __restrict__ fr,
                      float* __restrict__ out)
{
    __shared__ float s[2][CPASS * SWINP];   // 36864 B

    int t    = threadIdx.x;
    int warp = t >> 5;
    int lane = t & 31;
    int seg  = blockIdx.x & 1;
    int y    = (blockIdx.x >> 1) & (HH - 1);
    int b    = blockIdx.x >> 10;
    int xs   = seg * WSEG;
    int wbeg = xs - PADL;                    // multiple of 4 -> 16B aligned

    // ---- per-pixel setup (compute lanes only: t < 480) ----
    int x = xs + t;
    float w = 0.f, mm1 = 0.f, m0 = 0.f, mp1 = 0.f;
    int off = 1;
    if (t < WSEG) {
        int ht = y >> 2, wt = x >> 2;
        int i  = y & 3,  j  = x & 3;
        int tb = (b * 3 * HT + ht) * WT + wt;
        float d  = __ldg(tp + tb);
        float dx = __ldg(tp + tb + HTWT);
        float dy = __ldg(tp + tb + 2 * HTWT);

        float sx  = (float)x - d - ((float)j - 1.5f) * dx - ((float)i - 1.5f) * dy;
        float x0f = floorf(sx);
        w  = sx - x0f;
        int x0 = (int)x0f;

        mm1 = (sx >= -1.f && sx <= (float)(WW - 2)) ? 1.f : 0.f;
        m0  = (sx >=  0.f && sx <= (float)(WW - 1)) ? 1.f : 0.f;
        mp1 = (sx >=  1.f && sx <= (float)(WW))     ? 1.f : 0.f;

        off = min(max(x0 - wbeg, 1), SWINP - 3);   // smem-safe; masked if clamped
    }

    const float* frrow = fr + (size_t)b * CCH * HW + (size_t)y * WW;
    const float* flp   = fl + (size_t)b * CCH * HW + (size_t)y * WW + x;

    // staging role: warp w -> channel (w>>1), half-window (w&1)
    int sc    = warp >> 1;                 // 0..7
    int kbase = (warp & 1) * (NF4 / 2);    // 0 or 72
    const float* ssrc0 = frrow + (size_t)sc * HW + wbeg;

    auto stage = [&](int pp, int bb) {
        const float* src = ssrc0 + (size_t)pp * CPASS * HW;
        float* dst = &s[bb][sc * SWINP];
#pragma unroll
        for (int r = 0; r < 3; r++) {
            int k4 = kbase + lane + r * 32;
            if (k4 < kbase + NF4 / 2) {
                int gx = wbeg + 4 * k4;
                unsigned sz = (gx >= 0 && gx < WW) ? 16u : 0u;
                cp_async16(dst + 4 * k4, src + 4 * k4, sz);
            }
        }
        cp_commit();
    };

    float am1 = 0.f, a0 = 0.f, ap1 = 0.f;
    float nm1 = -mm1, n0 = -m0, np1 = -mp1;   // for fmaf(-m, lerp, a)

    // ---- prologue: stage pass 0 ----
    stage(0, 0);
    cp_wait_all();
    __syncthreads();

#pragma unroll
    for (int p = 0; p < NPASS; p++) {
        // issue staging for pass p+1 into the other buffer (async)
        if (p < NPASS - 1) stage(p + 1, (p + 1) & 1);

        // ---- compute pass p: explicit 1-channel software pipeline ----
        if (t < WSEG) {
            const float* buf = s[p & 1] + off;
            const float* flc = flp + (size_t)(p * CPASS) * HW;

            // preload channel 0
            float g0 = buf[-1], g1 = buf[0], g2 = buf[1], g3 = buf[2];
            float a  = __ldcs(flc);

#pragma unroll
            for (int c = 0; c < CPASS; c++) {
                // prefetch channel c+1 (taps + fea_l) before using channel c
                float h0, h1, h2, h3, an;
                if (c < CPASS - 1) {
                    const float* q = buf + (c + 1) * SWINP;
                    h0 = q[-1]; h1 = q[0]; h2 = q[1]; h3 = q[2];
                    an = __ldcs(flc + (size_t)(c + 1) * HW);
                }
                // accumulate channel c
                float lm1 = fmaf(w, g3 - g2, g2);
                float l0  = fmaf(w, g2 - g1, g1);
                float lp1 = fmaf(w, g1 - g0, g0);
                am1 += fabsf(fmaf(nm1, lm1, a));
                a0  += fabsf(fmaf(n0,  l0,  a));
                ap1 += fabsf(fmaf(np1, lp1, a));
                if (c < CPASS - 1) { g0 = h0; g1 = h1; g2 = h2; g3 = h3; a = an; }
            }
        }

        cp_wait_all();
        __syncthreads();
    }

    if (t < WSEG) {
        int ht = y >> 2, wt = x >> 2;
        int i  = y & 3,  j  = x & 3;
        int ob = (b * 48 * HT + ht) * WT + wt + (i * 4 + j) * HTWT;
        out[ob]             = am1;
        out[ob + 16 * HTWT] = a0;
        out[ob + 32 * HTWT] = ap1;
    }
}

extern "C" void kernel_launch(void* const* d_in, const int* in_sizes, int n_in,
                              void* d_out, int out_size)
{
    const float* tp = nullptr;
    const float* big[2] = {nullptr, nullptr};
    int nbig = 0;
    for (int k = 0; k < n_in; k++) {
        if (in_sizes[k] == BATCH * 3 * HTWT) {
            tp = (const float*)d_in[k];
        } else if (nbig < 2) {
            big[nbig++] = (const float*)d_in[k];
        }
    }
    const float* fl = big[0];
    const float* fr = big[1];
    float* out = (float*)d_out;

    int blocks = BATCH * HH * 2;   // 4096
    tile_warp_kernel<<<blocks, NTHR>>>(tp, fl, fr, out);
}